// round 15
// baseline (speedup 1.0000x reference)
#include <cuda_runtime.h>
#include <cuda_fp16.h>
#include <cstdint>
#include <math.h>

#define TT 1024
#define DD 1024
#define HN 16
#define HD 64
#define LAT 512
#define RDIM 64
#define NL 8
#define VV 32000
#define FF 4096

typedef __half h16;

// ---- fused weight layout ---------------------------------------------------
#define W1SZ   (1088*1024)
#define W2SZ   (2048*512)
#define OFF_W1  0
#define OFF_W2A (OFF_W1  + NL*W1SZ)
#define OFF_W2B (OFF_W2A + NL*W2SZ)
#define OFF_WO  (OFF_W2B + NL*W2SZ)
#define OFF_FC1 (OFF_WO  + NL*DD*DD)
#define OFF_FC2 (OFF_FC1 + NL*FF*DD)
#define OFF_LMH (OFF_FC2 + NL*DD*FF)
#define TOTAL_W (OFF_LMH + VV*DD)

__device__ __align__(256) h16 g_wh[TOTAL_W];

// ---- activation scratch ------------------------------------------------------
__device__ __align__(256) float g_x [TT*DD];
__device__ __align__(256) h16 g_c1h[TT*1088];      // ql | ckv | kr
__device__ __align__(256) h16 g_qqr[TT*2048];      // q | qr
__device__ __align__(256) h16 g_kv [TT*2048];      // k | v
__device__ __align__(256) h16 g_atth[TT*DD];
__device__ __align__(256) h16 g_tmph[TT*FF];
__device__ __align__(256) h16 g_xh [TT*DD];

// ---- helpers -----------------------------------------------------------------
__device__ __forceinline__ uint32_t packh(h16 a, h16 b) {
    __half2 t = __halves2half2(a, b);
    return *reinterpret_cast<uint32_t*>(&t);
}
__device__ __forceinline__ uint32_t pack2h(float x, float y) {
    __half2 t = __floats2half2_rn(x, y);
    return *reinterpret_cast<uint32_t*>(&t);
}
__device__ __forceinline__ float ssq_word(uint32_t w) {
    __half2 h = *reinterpret_cast<__half2*>(&w);
    float2 f = __half22float2(h);
    return f.x * f.x + f.y * f.y;
}

__device__ __forceinline__ void cp16(uint32_t dst, const void* src) {
    asm volatile("cp.async.cg.shared.global [%0], [%1], 16;" :: "r"(dst), "l"(src));
}
#define CP_COMMIT() asm volatile("cp.async.commit_group;" ::: "memory")
template<int N> __device__ __forceinline__ void cp_wait() {
    asm volatile("cp.async.wait_group %0;" :: "n"(N) : "memory");
}

__device__ __forceinline__ void mma16816(float* c, const uint32_t* a, const uint32_t* b) {
    asm volatile(
        "mma.sync.aligned.m16n8k16.row.col.f32.f16.f16.f32 "
        "{%0,%1,%2,%3}, {%4,%5,%6,%7}, {%8,%9}, {%0,%1,%2,%3};"
        : "+f"(c[0]), "+f"(c[1]), "+f"(c[2]), "+f"(c[3])
        : "r"(a[0]), "r"(a[1]), "r"(a[2]), "r"(a[3]), "r"(b[0]), "r"(b[1]));
}

__device__ __forceinline__ void ldm4(uint32_t* r, uint32_t addr) {
    asm volatile("ldmatrix.sync.aligned.m8n8.x4.shared.b16 {%0,%1,%2,%3}, [%4];"
        : "=r"(r[0]), "=r"(r[1]), "=r"(r[2]), "=r"(r[3]) : "r"(addr));
}

__device__ __forceinline__ int sadr(int row, int w) {
    return row * 16 + (((w >> 2) ^ (row & 3)) << 2) + (w & 3);
}

// ---- strided weight conversion (1 or 2 sources via grid.z) ----------------------
__global__ void cvt_h_s(const float* __restrict__ in0, const float* __restrict__ in1,
                        h16* __restrict__ hi, int n, int cshift, int dstride,
                        int doff0, int doff1) {
    const float* in = blockIdx.z ? in1 : in0;
    int doff = blockIdx.z ? doff1 : doff0;
    int i = (blockIdx.x * blockDim.x + threadIdx.x) * 8;
    int stride = gridDim.x * blockDim.x * 8;
    int cmask = (1 << cshift) - 1;
    for (; i < n; i += stride) {
        size_t di = (size_t)(i >> cshift) * dstride + doff + (i & cmask);
        float4 a = *(const float4*)(in + i);
        float4 b = *(const float4*)(in + i + 4);
        *(uint4*)(hi + di) = make_uint4(pack2h(a.x, a.y), pack2h(a.z, a.w),
                                        pack2h(b.x, b.y), pack2h(b.z, b.w));
    }
}

// ---- embedding ---------------------------------------------------------------------
__global__ void embed_kernel(const int* __restrict__ idx, const float* __restrict__ wte,
                             float* __restrict__ x) {
    int t = blockIdx.x;
    int row = idx[t];
    float4 v = *(const float4*)(wte + (size_t)row * DD + threadIdx.x * 4);
    *(float4*)(x + (size_t)t * DD + threadIdx.x * 4) = v;
}

// ---- init rmsnorm (x -> normalized x fp32 + fp16) ------------------------------------
__global__ void rmsnorm_kernel(const float* __restrict__ in, float* __restrict__ out,
                               h16* __restrict__ ohi) {
    __shared__ float red[8];
    int row = blockIdx.x, tid = threadIdx.x;
    float4 v = *(const float4*)(in + (size_t)row * DD + tid * 4);
    float s = v.x*v.x + v.y*v.y + v.z*v.z + v.w*v.w;
    #pragma unroll
    for (int o = 16; o > 0; o >>= 1) s += __shfl_xor_sync(0xffffffff, s, o);
    if ((tid & 31) == 0) red[tid >> 5] = s;
    __syncthreads();
    if (tid < 8) {
        float t2 = red[tid];
        #pragma unroll
        for (int o = 4; o > 0; o >>= 1) t2 += __shfl_xor_sync(0xff, t2, o);
        if (tid == 0) red[0] = t2;
    }
    __syncthreads();
    float r = rsqrtf(red[0] / (float)DD + 1e-5f);
    float4 o4 = make_float4(v.x*r, v.y*r, v.z*r, v.w*r);
    *(float4*)(out + (size_t)row * DD + tid * 4) = o4;
    size_t b = (size_t)row * DD + tid * 4;
    *(uint2*)(ohi + b) = make_uint2(pack2h(o4.x, o4.y), pack2h(o4.z, o4.w));
}

// ---- RoPE on fp16 ---------------------------------------------------------------------
__global__ void rope_kernel(h16* __restrict__ qqr, h16* __restrict__ c1h) {
    int t = blockIdx.x, h = blockIdx.y, j = threadIdx.x;
    float f = powf(10000.f, -(float)j / 32.f);
    float sv, cv;
    sincosf((float)t * f, &sv, &cv);
    h16* p = (h < 16) ? (qqr + (size_t)t * 2048 + 1024 + h * RDIM)
                      : (c1h + (size_t)t * 1088 + 1024);
    float x0 = __half2float(p[j]), x1 = __half2float(p[j + 32]);
    p[j]      = __float2half_rn(x0 * cv - x1 * sv);
    p[j + 32] = __float2half_rn(x1 * cv + x0 * sv);
}

// ---- fp16 NT GEMM, 4-stage pipeline; RMS scale fused via fragment ssq -----------------
template<int BM, int BN, bool RMS>
__global__ void __launch_bounds__(256) gemm_mma(
    const h16* __restrict__ Ah_, const h16* __restrict__ Ah2_, int lda,
    const h16* __restrict__ Bh_, const h16* __restrict__ Bh2_,
    float* __restrict__ C, int ldc, const float* __restrict__ Rres,
    h16* __restrict__ Chi_, h16* __restrict__ Chi2_,
    int K, int relu)
{
    extern __shared__ uint32_t smw[];
    constexpr int AT  = BM * 16;
    constexpr int BT  = BN * 16;
    constexpr int STG = AT + BT;
    constexpr int NT  = BN / 16;
    constexpr int MT  = BM / 64;
    constexpr int D   = 4;

    const h16* Ah  = blockIdx.z ? Ah2_  : Ah_;
    const h16* Bh  = blockIdx.z ? Bh2_  : Bh_;
    h16*       Chi = blockIdx.z ? Chi2_ : Chi_;

    int tid = threadIdx.x, lane = tid & 31, w = tid >> 5;
    int wm = w & 3, wn = w >> 2;
    int bm = blockIdx.y * BM, bn = blockIdx.x * BN;
    int la = lane & 3, lr = lane >> 2;

    int rowl = (lane & 7) | (((lane >> 3) & 1) << 3);
    int csel = (lane >> 4) << 2;

    uint32_t sbase = (uint32_t)__cvta_generic_to_shared(smw);

    auto load_stage = [&](int i, int st) {
        int k0 = i * 32;
        uint32_t so = sbase + (uint32_t)(st * STG) * 4;
        #pragma unroll
        for (int e0 = 0; e0 < BM * 4; e0 += 256) {
            int e = e0 + tid;
            int r = e >> 2, kq = e & 3;
            size_t g = (size_t)(bm + r) * lda + k0 + kq * 8;
            uint32_t d = so + (uint32_t)(r * 16 + ((kq ^ (r & 3)) << 2)) * 4;
            cp16(d, Ah + g);
        }
        #pragma unroll
        for (int e0 = 0; e0 < BN * 4; e0 += 256) {
            int e = e0 + tid;
            int r = e >> 2, kq = e & 3;
            size_t g = (size_t)(bn + r) * K + k0 + kq * 8;
            uint32_t d = so + (uint32_t)(AT + r * 16 + ((kq ^ (r & 3)) << 2)) * 4;
            cp16(d, Bh + g);
        }
        CP_COMMIT();
    };

    float acc[MT][NT][4];
    #pragma unroll
    for (int mt = 0; mt < MT; mt++)
        #pragma unroll
        for (int nt = 0; nt < NT; nt++)
            #pragma unroll
            for (int c = 0; c < 4; c++) acc[mt][nt][c] = 0.f;

    float ssA[MT][2];
    #pragma unroll
    for (int mt = 0; mt < MT; mt++) { ssA[mt][0] = 0.f; ssA[mt][1] = 0.f; }

    int nk = K >> 5;
    #pragma unroll
    for (int s = 0; s < D - 1; s++) load_stage(s, s);

    for (int i = 0; i < nk; i++) {
        cp_wait<D - 2>();
        __syncthreads();
        if (i + D - 1 < nk) load_stage(i + D - 1, (i + D - 1) % D);
        else                CP_COMMIT();

        uint32_t SaB = sbase + (uint32_t)((i % D) * STG) * 4;
        uint32_t SbB = SaB + (uint32_t)AT * 4;
        #pragma unroll
        for (int ks = 0; ks < 2; ks++) {
            int w0 = ks * 8 + csel;
            uint32_t ah[MT][4];
            #pragma unroll
            for (int mt = 0; mt < MT; mt++) {
                uint32_t aaddr = SaB + (uint32_t)sadr(wm * (BM / 4) + mt * 16 + rowl, w0) * 4;
                ldm4(ah[mt], aaddr);
            }
            if (RMS && wn == 0) {
                // fragment-based ssq: each (lr,la) lane owns unique A elements
                #pragma unroll
                for (int mt = 0; mt < MT; mt++) {
                    ssA[mt][0] += ssq_word(ah[mt][0]) + ssq_word(ah[mt][2]);
                    ssA[mt][1] += ssq_word(ah[mt][1]) + ssq_word(ah[mt][3]);
                }
            }
            #pragma unroll
            for (int nt2 = 0; nt2 < NT / 2; nt2++) {
                uint32_t baddr = SbB + (uint32_t)sadr(wn * (BN / 2) + nt2 * 16 + rowl, w0) * 4;
                uint32_t bb[4];
                ldm4(bb, baddr);
                uint32_t b0[2] = { bb[0], bb[2] };
                uint32_t b1[2] = { bb[1], bb[3] };
                #pragma unroll
                for (int mt = 0; mt < MT; mt++) {
                    mma16816(acc[mt][2 * nt2],     ah[mt], b0);
                    mma16816(acc[mt][2 * nt2 + 1], ah[mt], b1);
                }
            }
        }
    }

    float* rf = (float*)smw;
    if (RMS) {
        __syncthreads();                     // all ldmatrix reads of smem done
        if (wn == 0) {
            #pragma unroll
            for (int mt = 0; mt < MT; mt++) {
                float s0 = ssA[mt][0], s1 = ssA[mt][1];
                s0 += __shfl_xor_sync(0xffffffff, s0, 1);
                s0 += __shfl_xor_sync(0xffffffff, s0, 2);
                s1 += __shfl_xor_sync(0xffffffff, s1, 1);
                s1 += __shfl_xor_sync(0xffffffff, s1, 2);
                if (la == 0) {
                    int rb = wm * (BM / 4) + mt * 16 + lr;
                    rf[rb]     = rsqrtf(s0 * (1.f / 1024.f) + 1e-5f);
                    rf[rb + 8] = rsqrtf(s1 * (1.f / 1024.f) + 1e-5f);
                }
            }
        }
        __syncthreads();
    }

    #pragma unroll
    for (int mt = 0; mt < MT; mt++) {
        #pragma unroll
        for (int nt = 0; nt < NT; nt++) {
            int col = bn + wn * (BN / 2) + nt * 8 + la * 2;
            #pragma unroll
            for (int half = 0; half < 2; half++) {
                int row = bm + wm * (BM / 4) + mt * 16 + lr + half * 8;
                float v0 = acc[mt][nt][half * 2 + 0];
                float v1 = acc[mt][nt][half * 2 + 1];
                if (RMS) { float r = rf[row - bm]; v0 *= r; v1 *= r; }
                size_t base = (size_t)row * ldc + col;
                if (Rres) {
                    float2 rr = *(const float2*)(Rres + base);
                    v0 += rr.x; v1 += rr.y;
                }
                if (relu) { v0 = fmaxf(v0, 0.f); v1 = fmaxf(v1, 0.f); }
                if (C) *(float2*)(C + base) = make_float2(v0, v1);
                if (Chi) *(uint32_t*)(Chi + base) = pack2h(v0, v1);
            }
        }
    }
}

// ---- flash attention, fp16 in/out, 1-pass MMA -------------------------------------------
#define QLD 2048
#define KRLD 1088
#define AQ 68
#define AV 36
#define ATTSM ((2*64*AQ + 64*AV) * 4 + 64*65*4 + (64+64+128+128) * 4)

__global__ void __launch_bounds__(256, 1) attn_mma(
    const h16* __restrict__ q,  const h16* __restrict__ qr,
    const h16* __restrict__ k,  const h16* __restrict__ v,
    const h16* __restrict__ kr,
    h16* __restrict__ atth)
{
    extern __shared__ uint32_t sw[];
    uint32_t* Qh = sw;
    uint32_t* Kh = Qh + 64 * AQ;
    uint32_t* Vh = Kh + 64 * AQ;
    float* Ob   = (float*)(Vh + 64 * AV);
    float* rowM = Ob + 64 * 65;
    float* rowL = rowM + 64;
    float* pm   = rowL + 64;
    float* ps   = pm + 128;

    int hh = blockIdx.y, tid = threadIdx.x;
    int lane = tid & 31, w = tid >> 5;
    int wm = w & 3, wn = w >> 2;
    int la = lane & 3, lr = lane >> 2;
    const float scale = rsqrtf(128.f);

    for (int half = 0; half < 2; half++) {
        int qt = half ? (15 - (int)blockIdx.x) : (int)blockIdx.x;

        for (int e = tid; e < 64 * 64; e += 256) {
            int r = e >> 6, wq = e & 63;
            int t = qt * 64 + r, d = wq * 2;
            const h16* src = (d < 64) ? (q + (size_t)t * QLD + hh * 64 + d)
                                      : (qr + (size_t)t * QLD + hh * 64 + (d - 64));
            Qh[r * AQ + wq] = *(const uint32_t*)src;
        }
        if (tid < 64) { rowM[tid] = -1e30f; rowL[tid] = 0.f; }

        float oacc[8][4];
        #pragma unroll
        for (int nt = 0; nt < 8; nt++)
            #pragma unroll
            for (int c = 0; c < 4; c++) oacc[nt][c] = 0.f;

        int rloc = wm * 16 + lr;

        for (int kt = 0; kt <= qt; kt++) {
            __syncthreads();

            for (int e = tid; e < 64 * 64; e += 256) {
                int r = e >> 6, wq = e & 63;
                int t = kt * 64 + r, d = wq * 2;
                const h16* src = (d < 64) ? (k + (size_t)t * QLD + hh * 64 + d)
                                          : (kr + (size_t)t * KRLD + (d - 64));
                Kh[r * AQ + wq] = *(const uint32_t*)src;
            }
            for (int e = tid; e < 64 * 32; e += 256) {
                int kp = e >> 6, d = e & 63;
                h16 v0 = v[(size_t)(kt * 64 + 2 * kp) * QLD + hh * 64 + d];
                h16 v1 = v[(size_t)(kt * 64 + 2 * kp + 1) * QLD + hh * 64 + d];
                Vh[d * AV + kp] = packh(v0, v1);
            }
            __syncthreads();

            float sacc[4][4];
            #pragma unroll
            for (int nt = 0; nt < 4; nt++)
                #pragma unroll
                for (int c = 0; c < 4; c++) sacc[nt][c] = 0.f;

            #pragma unroll
            for (int kk = 0; kk < 8; kk++) {
                int w0 = kk * 8 + la;
                uint32_t ah[4];
                ah[0] = Qh[rloc * AQ + w0];        ah[1] = Qh[(rloc + 8) * AQ + w0];
                ah[2] = Qh[rloc * AQ + w0 + 4];    ah[3] = Qh[(rloc + 8) * AQ + w0 + 4];
                #pragma unroll
                for (int nt = 0; nt < 4; nt++) {
                    int n0 = wn * 32 + nt * 8 + lr;
                    uint32_t bh[2] = { Kh[n0 * AQ + w0], Kh[n0 * AQ + w0 + 4] };
                    mma16816(sacc[nt], ah, bh);
                }
            }

            int rgA = qt * 64 + rloc, rgB = rgA + 8;
            #pragma unroll
            for (int nt = 0; nt < 4; nt++) {
                int cg = kt * 64 + wn * 32 + nt * 8 + 2 * la;
                sacc[nt][0] = (cg     <= rgA) ? sacc[nt][0] * scale : -1e30f;
                sacc[nt][1] = (cg + 1 <= rgA) ? sacc[nt][1] * scale : -1e30f;
                sacc[nt][2] = (cg     <= rgB) ? sacc[nt][2] * scale : -1e30f;
                sacc[nt][3] = (cg + 1 <= rgB) ? sacc[nt][3] * scale : -1e30f;
            }

            float mA = -1e30f, mB = -1e30f;
            #pragma unroll
            for (int nt = 0; nt < 4; nt++) {
                mA = fmaxf(mA, fmaxf(sacc[nt][0], sacc[nt][1]));
                mB = fmaxf(mB, fmaxf(sacc[nt][2], sacc[nt][3]));
            }
            mA = fmaxf(mA, __shfl_xor_sync(0xffffffff, mA, 1));
            mA = fmaxf(mA, __shfl_xor_sync(0xffffffff, mA, 2));
            mB = fmaxf(mB, __shfl_xor_sync(0xffffffff, mB, 1));
            mB = fmaxf(mB, __shfl_xor_sync(0xffffffff, mB, 2));
            if (la == 0) { pm[wn * 64 + rloc] = mA; pm[wn * 64 + rloc + 8] = mB; }
            __syncthreads();

            float moA = rowM[rloc], moB = rowM[rloc + 8];
            float mnA = fmaxf(moA, fmaxf(pm[rloc], pm[64 + rloc]));
            float mnB = fmaxf(moB, fmaxf(pm[rloc + 8], pm[64 + rloc + 8]));
            float alA = __expf(moA - mnA), alB = __expf(moB - mnB);

            float sA = 0.f, sB = 0.f;
            #pragma unroll
            for (int nt = 0; nt < 4; nt++) {
                sacc[nt][0] = __expf(sacc[nt][0] - mnA);
                sacc[nt][1] = __expf(sacc[nt][1] - mnA);
                sacc[nt][2] = __expf(sacc[nt][2] - mnB);
                sacc[nt][3] = __expf(sacc[nt][3] - mnB);
                sA += sacc[nt][0] + sacc[nt][1];
                sB += sacc[nt][2] + sacc[nt][3];
            }
            #pragma unroll
            for (int nt = 0; nt < 8; nt++) {
                oacc[nt][0] *= alA; oacc[nt][1] *= alA;
                oacc[nt][2] *= alB; oacc[nt][3] *= alB;
            }
            sA += __shfl_xor_sync(0xffffffff, sA, 1);
            sA += __shfl_xor_sync(0xffffffff, sA, 2);
            sB += __shfl_xor_sync(0xffffffff, sB, 1);
            sB += __shfl_xor_sync(0xffffffff, sB, 2);
            __syncthreads();
            if (la == 0) { ps[wn * 64 + rloc] = sA; ps[wn * 64 + rloc + 8] = sB; }
            if (wn == 0 && la == 0) { rowM[rloc] = mnA; rowM[rloc + 8] = mnB; }
            __syncthreads();
            if (wn == 0 && la == 0) {
                rowL[rloc]     = rowL[rloc]     * alA + ps[rloc]     + ps[64 + rloc];
                rowL[rloc + 8] = rowL[rloc + 8] * alB + ps[rloc + 8] + ps[64 + rloc + 8];
            }

            #pragma unroll
            for (int kc = 0; kc < 2; kc++) {
                uint32_t phi[4];
                phi[0] = pack2h(sacc[2*kc][0],   sacc[2*kc][1]);
                phi[1] = pack2h(sacc[2*kc][2],   sacc[2*kc][3]);
                phi[2] = pack2h(sacc[2*kc+1][0], sacc[2*kc+1][1]);
                phi[3] = pack2h(sacc[2*kc+1][2], sacc[2*kc+1][3]);
                int kw = wn * 16 + kc * 8 + la;
                #pragma unroll
                for (int nt = 0; nt < 8; nt++) {
                    int d0 = nt * 8 + lr;
                    uint32_t bh[2] = { Vh[d0 * AV + kw], Vh[d0 * AV + kw + 4] };
                    mma16816(oacc[nt], phi, bh);
                }
            }
        }

        __syncthreads();
        if (wn == 0) {
            #pragma unroll
            for (int nt = 0; nt < 8; nt++) {
                int c0 = nt * 8 + 2 * la;
                Ob[rloc * 65 + c0]         = oacc[nt][0];
                Ob[rloc * 65 + c0 + 1]     = oacc[nt][1];
                Ob[(rloc+8) * 65 + c0]     = oacc[nt][2];
                Ob[(rloc+8) * 65 + c0 + 1] = oacc[nt][3];
            }
        }
        __syncthreads();
        if (wn == 1) {
            #pragma unroll
            for (int nt = 0; nt < 8; nt++) {
                int c0 = nt * 8 + 2 * la;
                Ob[rloc * 65 + c0]         += oacc[nt][0];
                Ob[rloc * 65 + c0 + 1]     += oacc[nt][1];
                Ob[(rloc+8) * 65 + c0]     += oacc[nt][2];
                Ob[(rloc+8) * 65 + c0 + 1] += oacc[nt][3];
            }
        }
        __syncthreads();
        for (int e = tid; e < 64 * 32; e += 256) {
            int r = e >> 5, d2 = (e & 31) * 2;
            float v0 = Ob[r * 65 + d2]     / rowL[r];
            float v1 = Ob[r * 65 + d2 + 1] / rowL[r];
            size_t o = (size_t)(qt * 64 + r) * DD + hh * 64 + d2;
            *(uint32_t*)(atth + o) = pack2h(v0, v1);
        }
        __syncthreads();
    }
}

// ---- host orchestration -------------------------------------------------------------
#define SMEMSZ(BM,BN) (4 * ((BM) + (BN)) * 64)

template<int BM, int BN, bool RMS>
static void gemmT(const h16* Ah, int lda, const h16* Bh,
                  float* C, int ldc, const float* R, h16* Ch,
                  int M, int N, int K, int relu) {
    dim3 grid(N / BN, M / BM, 1);
    gemm_mma<BM, BN, RMS><<<grid, 256, SMEMSZ(BM, BN)>>>(Ah, Ah, lda, Bh, Bh, C, ldc, R, Ch, Ch, K, relu);
}
template<int BM, int BN>
static void gemmT2(const h16* Ah, const h16* Ah2, int lda,
                   const h16* Bh, const h16* Bh2,
                   h16* Ch, h16* Ch2, int ldc,
                   int M, int N, int K) {
    dim3 grid(N / BN, M / BM, 2);
    gemm_mma<BM, BN, false><<<grid, 256, SMEMSZ(BM, BN)>>>(Ah, Ah2, lda, Bh, Bh2,
                                                           nullptr, ldc, nullptr, Ch, Ch2, K, 0);
}
static void cvt1(const float* in, h16* dst, int n, int cs, int ds, int off) {
    cvt_h_s<<<dim3(2048,1,1),256>>>(in, in, dst, n, cs, ds, off, off);
}
static void cvt2(const float* in0, const float* in1, h16* dst, int n, int cs, int ds,
                 int off0, int off1) {
    cvt_h_s<<<dim3(1536,1,2),256>>>(in0, in1, dst, n, cs, ds, off0, off1);
}

extern "C" void kernel_launch(void* const* d_in, const int* in_sizes, int n_in,
                              void* d_out, int out_size) {
    const int*   idx     = (const int*)  d_in[0];
    const float* wte     = (const float*)d_in[1];
    const float* wqdown  = (const float*)d_in[2];
    const float* wqup    = (const float*)d_in[3];
    const float* wqr     = (const float*)d_in[4];
    const float* wkvdown = (const float*)d_in[5];
    const float* wkup    = (const float*)d_in[6];
    const float* wvup    = (const float*)d_in[7];
    const float* wkr     = (const float*)d_in[8];
    const float* wo      = (const float*)d_in[9];
    const float* fc1     = (const float*)d_in[10];
    const float* fc2     = (const float*)d_in[11];
    const float* lm_head = (const float*)d_in[12];
    float* out = (float*)d_out;

    cudaFuncSetAttribute((void*)gemm_mma<128,128,false>, cudaFuncAttributeMaxDynamicSharedMemorySize, SMEMSZ(128,128));
    cudaFuncSetAttribute((void*)gemm_mma<128,128,true>,  cudaFuncAttributeMaxDynamicSharedMemorySize, SMEMSZ(128,128));
    cudaFuncSetAttribute((void*)gemm_mma<128,64,true>,   cudaFuncAttributeMaxDynamicSharedMemorySize, SMEMSZ(128,64));
    cudaFuncSetAttribute((void*)gemm_mma<64,128,false>,  cudaFuncAttributeMaxDynamicSharedMemorySize, SMEMSZ(64,128));
    cudaFuncSetAttribute((void*)attn_mma,                cudaFuncAttributeMaxDynamicSharedMemorySize, ATTSM);

    void* p;
    cudaGetSymbolAddress(&p, g_x);    float* x   = (float*)p;
    cudaGetSymbolAddress(&p, g_c1h);  h16* c1h   = (h16*)p;
    cudaGetSymbolAddress(&p, g_qqr);  h16* qqr   = (h16*)p;
    cudaGetSymbolAddress(&p, g_kv);   h16* kv    = (h16*)p;
    cudaGetSymbolAddress(&p, g_atth); h16* atth  = (h16*)p;
    cudaGetSymbolAddress(&p, g_tmph); h16* tmph  = (h16*)p;
    cudaGetSymbolAddress(&p, g_xh);   h16* xh    = (h16*)p;
    cudaGetSymbolAddress(&p, g_wh);   h16* wh    = (h16*)p;

    // ---- fused weight layout (8 launches) ----
    cvt2(wqdown, wkvdown, wh+OFF_W1, NL*512*1024, 19, W1SZ, 0, 512*1024);
    cvt1(wkr,  wh+OFF_W1,  NL*64*1024,  16, W1SZ, 1024*1024);
    cvt2(wqup, wqr,  wh+OFF_W2A, NL*1024*512, 19, W2SZ, 0, 1024*512);
    cvt2(wkup, wvup, wh+OFF_W2B, NL*1024*512, 19, W2SZ, 0, 1024*512);
    cvt1(wo,      wh+OFF_WO,  NL*DD*DD, 20, DD*DD, 0);
    cvt1(fc1,     wh+OFF_FC1, NL*FF*DD, 22, FF*DD, 0);
    cvt1(fc2,     wh+OFF_FC2, NL*DD*FF, 22, DD*FF, 0);
    cvt1(lm_head, wh+OFF_LMH, VV*DD,    30, VV*DD, 0);

    embed_kernel<<<TT, 256>>>(idx, wte, x);
    rmsnorm_kernel<<<TT, 256>>>(x, x, xh);   // init: x normalized, xh = fp16(x)

    for (int l = 0; l < NL; l++) {
        const h16* w1  = wh + OFF_W1  + (size_t)l * W1SZ;
        const h16* w2a = wh + OFF_W2A + (size_t)l * W2SZ;
        const h16* w2b = wh + OFF_W2B + (size_t)l * W2SZ;
        const h16* wol = wh + OFF_WO  + (size_t)l * DD*DD;
        const h16* f1  = wh + OFF_FC1 + (size_t)l * FF*DD;
        const h16* f2  = wh + OFF_FC2 + (size_t)l * DD*FF;

        gemmT<128,64,true>(xh, DD, w1, nullptr, 1088, nullptr, c1h, TT, 1088, DD, 0);
        gemmT2<128,128>(c1h, c1h + 512, 1088, w2a, w2b, qqr, kv, 2048, TT, 2048, LAT);

        rope_kernel<<<dim3(TT, 17), 32>>>(qqr, c1h);

        attn_mma<<<dim3(8, 16), 256, ATTSM>>>(qqr, qqr + 1024, kv, kv + 1024, c1h + 1024, atth);

        gemmT<64,128,false>(atth, DD, wol, x, DD, x, xh, TT, DD, DD, 0);

        gemmT<128,128,true>(xh, DD, f1, nullptr, FF, nullptr, tmph, TT, FF, DD, 1);
        bool last = (l == NL - 1);
        gemmT<64,128,false>(tmph, FF, f2, x, DD, x, xh, TT, DD, FF, 0);
    }

    gemmT<128,128,false>(xh, DD, wh + OFF_LMH, out, VV, nullptr, nullptr, TT, VV, DD, 0);
}

// round 16
// speedup vs baseline: 1.1135x; 1.1135x over previous
#include <cuda_runtime.h>
#include <cuda_fp16.h>
#include <cstdint>
#include <math.h>

#define TT 1024
#define DD 1024
#define HN 16
#define HD 64
#define LAT 512
#define RDIM 64
#define NL 8
#define VV 32000
#define FF 4096

typedef __half h16;

// ---- fused weight layout ---------------------------------------------------
#define W1SZ   (1088*1024)
#define W2SZ   (2048*512)
#define OFF_W1  0
#define OFF_W2A (OFF_W1  + NL*W1SZ)
#define OFF_W2B (OFF_W2A + NL*W2SZ)
#define OFF_WO  (OFF_W2B + NL*W2SZ)
#define OFF_FC1 (OFF_WO  + NL*DD*DD)
#define OFF_FC2 (OFF_FC1 + NL*FF*DD)
#define OFF_LMH (OFF_FC2 + NL*DD*FF)
#define TOTAL_W (OFF_LMH + VV*DD)

__device__ __align__(256) h16 g_wh[TOTAL_W];

// ---- activation scratch ------------------------------------------------------
__device__ __align__(256) float g_x [TT*DD];
__device__ __align__(256) h16 g_c1h[TT*1088];      // ql | ckv | kr
__device__ __align__(256) h16 g_qqr[TT*2048];      // q | qr
__device__ __align__(256) h16 g_kv [TT*2048];      // k | v
__device__ __align__(256) h16 g_atth[TT*DD];
__device__ __align__(256) h16 g_tmph[TT*FF];
__device__ __align__(256) h16 g_xh [TT*DD];

// ---- helpers -----------------------------------------------------------------
__device__ __forceinline__ uint32_t packh(h16 a, h16 b) {
    __half2 t = __halves2half2(a, b);
    return *reinterpret_cast<uint32_t*>(&t);
}
__device__ __forceinline__ uint32_t pack2h(float x, float y) {
    __half2 t = __floats2half2_rn(x, y);
    return *reinterpret_cast<uint32_t*>(&t);
}
__device__ __forceinline__ float ssq_word(uint32_t w) {
    __half2 h = *reinterpret_cast<__half2*>(&w);
    float2 f = __half22float2(h);
    return f.x * f.x + f.y * f.y;
}

__device__ __forceinline__ void cp16(uint32_t dst, const void* src) {
    asm volatile("cp.async.cg.shared.global [%0], [%1], 16;" :: "r"(dst), "l"(src));
}
#define CP_COMMIT() asm volatile("cp.async.commit_group;" ::: "memory")
template<int N> __device__ __forceinline__ void cp_wait() {
    asm volatile("cp.async.wait_group %0;" :: "n"(N) : "memory");
}

__device__ __forceinline__ void mma16816(float* c, const uint32_t* a, const uint32_t* b) {
    asm volatile(
        "mma.sync.aligned.m16n8k16.row.col.f32.f16.f16.f32 "
        "{%0,%1,%2,%3}, {%4,%5,%6,%7}, {%8,%9}, {%0,%1,%2,%3};"
        : "+f"(c[0]), "+f"(c[1]), "+f"(c[2]), "+f"(c[3])
        : "r"(a[0]), "r"(a[1]), "r"(a[2]), "r"(a[3]), "r"(b[0]), "r"(b[1]));
}

__device__ __forceinline__ void ldm4(uint32_t* r, uint32_t addr) {
    asm volatile("ldmatrix.sync.aligned.m8n8.x4.shared.b16 {%0,%1,%2,%3}, [%4];"
        : "=r"(r[0]), "=r"(r[1]), "=r"(r[2]), "=r"(r[3]) : "r"(addr));
}

__device__ __forceinline__ int sadr(int row, int w) {
    return row * 16 + (((w >> 2) ^ (row & 3)) << 2) + (w & 3);
}

// ---- strided weight conversion (1 or 2 sources via grid.z) ----------------------
__global__ void cvt_h_s(const float* __restrict__ in0, const float* __restrict__ in1,
                        h16* __restrict__ hi, int n, int cshift, int dstride,
                        int doff0, int doff1) {
    const float* in = blockIdx.z ? in1 : in0;
    int doff = blockIdx.z ? doff1 : doff0;
    int i = (blockIdx.x * blockDim.x + threadIdx.x) * 8;
    int stride = gridDim.x * blockDim.x * 8;
    int cmask = (1 << cshift) - 1;
    for (; i < n; i += stride) {
        size_t di = (size_t)(i >> cshift) * dstride + doff + (i & cmask);
        float4 a = *(const float4*)(in + i);
        float4 b = *(const float4*)(in + i + 4);
        *(uint4*)(hi + di) = make_uint4(pack2h(a.x, a.y), pack2h(a.z, a.w),
                                        pack2h(b.x, b.y), pack2h(b.z, b.w));
    }
}

// ---- embedding ---------------------------------------------------------------------
__global__ void embed_kernel(const int* __restrict__ idx, const float* __restrict__ wte,
                             float* __restrict__ x) {
    int t = blockIdx.x;
    int row = idx[t];
    float4 v = *(const float4*)(wte + (size_t)row * DD + threadIdx.x * 4);
    *(float4*)(x + (size_t)t * DD + threadIdx.x * 4) = v;
}

// ---- init rmsnorm ---------------------------------------------------------------------
__global__ void rmsnorm_kernel(const float* __restrict__ in, float* __restrict__ out,
                               h16* __restrict__ ohi) {
    __shared__ float red[8];
    int row = blockIdx.x, tid = threadIdx.x;
    float4 v = *(const float4*)(in + (size_t)row * DD + tid * 4);
    float s = v.x*v.x + v.y*v.y + v.z*v.z + v.w*v.w;
    #pragma unroll
    for (int o = 16; o > 0; o >>= 1) s += __shfl_xor_sync(0xffffffff, s, o);
    if ((tid & 31) == 0) red[tid >> 5] = s;
    __syncthreads();
    if (tid < 8) {
        float t2 = red[tid];
        #pragma unroll
        for (int o = 4; o > 0; o >>= 1) t2 += __shfl_xor_sync(0xff, t2, o);
        if (tid == 0) red[0] = t2;
    }
    __syncthreads();
    float r = rsqrtf(red[0] / (float)DD + 1e-5f);
    float4 o4 = make_float4(v.x*r, v.y*r, v.z*r, v.w*r);
    *(float4*)(out + (size_t)row * DD + tid * 4) = o4;
    size_t b = (size_t)row * DD + tid * 4;
    *(uint2*)(ohi + b) = make_uint2(pack2h(o4.x, o4.y), pack2h(o4.z, o4.w));
}

// ---- RoPE on fp16 -----------------------------------------------------------------------
__global__ void rope_kernel(h16* __restrict__ qqr, h16* __restrict__ c1h) {
    int t = blockIdx.x, h = blockIdx.y, j = threadIdx.x;
    float f = powf(10000.f, -(float)j / 32.f);
    float sv, cv;
    sincosf((float)t * f, &sv, &cv);
    h16* p = (h < 16) ? (qqr + (size_t)t * 2048 + 1024 + h * RDIM)
                      : (c1h + (size_t)t * 1088 + 1024);
    float x0 = __half2float(p[j]), x1 = __half2float(p[j + 32]);
    p[j]      = __float2half_rn(x0 * cv - x1 * sv);
    p[j + 32] = __float2half_rn(x1 * cv + x0 * sv);
}

// ---- fp16 NT GEMM, 4-stage pipeline; RMS scale fused via fragment ssq -----------------
template<int BM, int BN, bool RMS>
__global__ void __launch_bounds__(256) gemm_mma(
    const h16* __restrict__ Ah_, const h16* __restrict__ Ah2_, int lda,
    const h16* __restrict__ Bh_, const h16* __restrict__ Bh2_,
    float* __restrict__ C, int ldc, const float* __restrict__ Rres,
    h16* __restrict__ Chi_, h16* __restrict__ Chi2_,
    int K, int relu)
{
    extern __shared__ uint32_t smw[];
    constexpr int AT  = BM * 16;
    constexpr int BT  = BN * 16;
    constexpr int STG = AT + BT;
    constexpr int NT  = BN / 16;
    constexpr int MT  = BM / 64;
    constexpr int D   = 4;

    const h16* Ah  = blockIdx.z ? Ah2_  : Ah_;
    const h16* Bh  = blockIdx.z ? Bh2_  : Bh_;
    h16*       Chi = blockIdx.z ? Chi2_ : Chi_;

    int tid = threadIdx.x, lane = tid & 31, w = tid >> 5;
    int wm = w & 3, wn = w >> 2;
    int bm = blockIdx.y * BM, bn = blockIdx.x * BN;
    int la = lane & 3, lr = lane >> 2;

    int rowl = (lane & 7) | (((lane >> 3) & 1) << 3);
    int csel = (lane >> 4) << 2;

    uint32_t sbase = (uint32_t)__cvta_generic_to_shared(smw);

    auto load_stage = [&](int i, int st) {
        int k0 = i * 32;
        uint32_t so = sbase + (uint32_t)(st * STG) * 4;
        #pragma unroll
        for (int e0 = 0; e0 < BM * 4; e0 += 256) {
            int e = e0 + tid;
            int r = e >> 2, kq = e & 3;
            size_t g = (size_t)(bm + r) * lda + k0 + kq * 8;
            uint32_t d = so + (uint32_t)(r * 16 + ((kq ^ (r & 3)) << 2)) * 4;
            cp16(d, Ah + g);
        }
        #pragma unroll
        for (int e0 = 0; e0 < BN * 4; e0 += 256) {
            int e = e0 + tid;
            int r = e >> 2, kq = e & 3;
            size_t g = (size_t)(bn + r) * K + k0 + kq * 8;
            uint32_t d = so + (uint32_t)(AT + r * 16 + ((kq ^ (r & 3)) << 2)) * 4;
            cp16(d, Bh + g);
        }
        CP_COMMIT();
    };

    float acc[MT][NT][4];
    #pragma unroll
    for (int mt = 0; mt < MT; mt++)
        #pragma unroll
        for (int nt = 0; nt < NT; nt++)
            #pragma unroll
            for (int c = 0; c < 4; c++) acc[mt][nt][c] = 0.f;

    float ssA[MT][2];
    #pragma unroll
    for (int mt = 0; mt < MT; mt++) { ssA[mt][0] = 0.f; ssA[mt][1] = 0.f; }

    int nk = K >> 5;
    #pragma unroll
    for (int s = 0; s < D - 1; s++) load_stage(s, s);

    for (int i = 0; i < nk; i++) {
        cp_wait<D - 2>();
        __syncthreads();
        if (i + D - 1 < nk) load_stage(i + D - 1, (i + D - 1) % D);
        else                CP_COMMIT();

        uint32_t SaB = sbase + (uint32_t)((i % D) * STG) * 4;
        uint32_t SbB = SaB + (uint32_t)AT * 4;
        #pragma unroll
        for (int ks = 0; ks < 2; ks++) {
            int w0 = ks * 8 + csel;
            uint32_t ah[MT][4];
            #pragma unroll
            for (int mt = 0; mt < MT; mt++) {
                uint32_t aaddr = SaB + (uint32_t)sadr(wm * (BM / 4) + mt * 16 + rowl, w0) * 4;
                ldm4(ah[mt], aaddr);
            }
            if (RMS && wn == 0) {
                #pragma unroll
                for (int mt = 0; mt < MT; mt++) {
                    ssA[mt][0] += ssq_word(ah[mt][0]) + ssq_word(ah[mt][2]);
                    ssA[mt][1] += ssq_word(ah[mt][1]) + ssq_word(ah[mt][3]);
                }
            }
            #pragma unroll
            for (int nt2 = 0; nt2 < NT / 2; nt2++) {
                uint32_t baddr = SbB + (uint32_t)sadr(wn * (BN / 2) + nt2 * 16 + rowl, w0) * 4;
                uint32_t bb[4];
                ldm4(bb, baddr);
                uint32_t b0[2] = { bb[0], bb[2] };
                uint32_t b1[2] = { bb[1], bb[3] };
                #pragma unroll
                for (int mt = 0; mt < MT; mt++) {
                    mma16816(acc[mt][2 * nt2],     ah[mt], b0);
                    mma16816(acc[mt][2 * nt2 + 1], ah[mt], b1);
                }
            }
        }
    }

    float* rf = (float*)smw;
    if (RMS) {
        __syncthreads();
        if (wn == 0) {
            #pragma unroll
            for (int mt = 0; mt < MT; mt++) {
                float s0 = ssA[mt][0], s1 = ssA[mt][1];
                s0 += __shfl_xor_sync(0xffffffff, s0, 1);
                s0 += __shfl_xor_sync(0xffffffff, s0, 2);
                s1 += __shfl_xor_sync(0xffffffff, s1, 1);
                s1 += __shfl_xor_sync(0xffffffff, s1, 2);
                if (la == 0) {
                    int rb = wm * (BM / 4) + mt * 16 + lr;
                    rf[rb]     = rsqrtf(s0 * (1.f / 1024.f) + 1e-5f);
                    rf[rb + 8] = rsqrtf(s1 * (1.f / 1024.f) + 1e-5f);
                }
            }
        }
        __syncthreads();
    }

    #pragma unroll
    for (int mt = 0; mt < MT; mt++) {
        #pragma unroll
        for (int nt = 0; nt < NT; nt++) {
            int col = bn + wn * (BN / 2) + nt * 8 + la * 2;
            #pragma unroll
            for (int half = 0; half < 2; half++) {
                int row = bm + wm * (BM / 4) + mt * 16 + lr + half * 8;
                float v0 = acc[mt][nt][half * 2 + 0];
                float v1 = acc[mt][nt][half * 2 + 1];
                if (RMS) { float r = rf[row - bm]; v0 *= r; v1 *= r; }
                size_t base = (size_t)row * ldc + col;
                if (Rres) {
                    float2 rr = *(const float2*)(Rres + base);
                    v0 += rr.x; v1 += rr.y;
                }
                if (relu) { v0 = fmaxf(v0, 0.f); v1 = fmaxf(v1, 0.f); }
                if (C) *(float2*)(C + base) = make_float2(v0, v1);
                if (Chi) *(uint32_t*)(Chi + base) = pack2h(v0, v1);
            }
        }
    }
}

// ---- flash attention: cp.async K double-buffer, reg V staging, 3 syncs/iter -----------
#define QLD 2048
#define KRLD 1088
#define AQ 68
#define AV 36
#define ATT_Q 0
#define ATT_K (64*AQ)
#define ATT_V (ATT_K + 2*64*AQ)
#define ATT_PM (ATT_V + 2*64*AV)
#define ATTSM ((ATT_PM + 128 + 128 + 64) * 4)

__global__ void __launch_bounds__(256, 1) attn_mma(
    const h16* __restrict__ q,  const h16* __restrict__ qr,
    const h16* __restrict__ k,  const h16* __restrict__ v,
    const h16* __restrict__ kr,
    h16* __restrict__ atth)
{
    extern __shared__ uint32_t sw[];
    uint32_t* Qh = sw + ATT_Q;
    uint32_t* Kb = sw + ATT_K;           // [2][64*AQ]
    uint32_t* Vb = sw + ATT_V;           // [2][64*AV]
    float* pm    = (float*)(sw + ATT_PM);   // [2][64]
    float* ps    = pm + 128;                // [2][64]
    float* rowLs = ps + 128;                // [64]
    float* Ob    = (float*)(sw + ATT_K);    // aliases K buffers post-loop

    uint32_t sbase = (uint32_t)__cvta_generic_to_shared(sw);
    int hh = blockIdx.y, tid = threadIdx.x;
    int lane = tid & 31, w = tid >> 5;
    int wm = w & 3, wn = w >> 2;
    int la = lane & 3, lr = lane >> 2;
    const float scale = rsqrtf(128.f);

    int vkp = tid >> 3;      // 0..31 (key pair)
    int vdc = tid & 7;       // 0..7  (16B d-chunk)

    for (int half = 0; half < 2; half++) {
        int qt = half ? (15 - (int)blockIdx.x) : (int)blockIdx.x;

        // Q fill (cp.async) + tile-0 K (cp.async) + V (regs->STS)
        for (int e = tid; e < 1024; e += 256) {
            int r = e >> 4, c = e & 15;
            int t = qt * 64 + r;
            const h16* src = (c < 8) ? (q + (size_t)t * QLD + hh * 64 + c * 8)
                                     : (qr + (size_t)t * QLD + hh * 64 + (c - 8) * 8);
            cp16(sbase + (uint32_t)(ATT_Q + r * AQ + c * 4) * 4, src);
        }
        for (int e = tid; e < 1024; e += 256) {
            int r = e >> 4, c = e & 15;
            const h16* src = (c < 8) ? (k + (size_t)r * QLD + hh * 64 + c * 8)
                                     : (kr + (size_t)r * KRLD + (c - 8) * 8);
            cp16(sbase + (uint32_t)(ATT_K + r * AQ + c * 4) * 4, src);
        }
        CP_COMMIT();
        {
            uint4 va = *(const uint4*)(v + (size_t)(2 * vkp) * QLD + hh * 64 + vdc * 8);
            uint4 vb = *(const uint4*)(v + (size_t)(2 * vkp + 1) * QLD + hh * 64 + vdc * 8);
            const h16* pa = (const h16*)&va; const h16* pb = (const h16*)&vb;
            #pragma unroll
            for (int j = 0; j < 8; j++)
                Vb[(vdc * 8 + j) * AV + vkp] = packh(pa[j], pb[j]);
        }
        cp_wait<0>();
        __syncthreads();

        float mstA = -1e30f, mstB = -1e30f, lstA = 0.f, lstB = 0.f;
        float oacc[8][4];
        #pragma unroll
        for (int nt = 0; nt < 8; nt++)
            #pragma unroll
            for (int c = 0; c < 4; c++) oacc[nt][c] = 0.f;

        int rloc = wm * 16 + lr;

        for (int kt = 0; kt <= qt; kt++) {
            int cur = kt & 1, nxt = cur ^ 1;
            bool pf = (kt < qt);
            uint4 va, vbv;
            if (pf) {
                int tn = (kt + 1) * 64;
                for (int e = tid; e < 1024; e += 256) {
                    int r = e >> 4, c = e & 15;
                    int t = tn + r;
                    const h16* src = (c < 8) ? (k + (size_t)t * QLD + hh * 64 + c * 8)
                                             : (kr + (size_t)t * KRLD + (c - 8) * 8);
                    cp16(sbase + (uint32_t)(ATT_K + nxt * 64 * AQ + r * AQ + c * 4) * 4, src);
                }
                CP_COMMIT();
                va  = *(const uint4*)(v + (size_t)(tn + 2 * vkp) * QLD + hh * 64 + vdc * 8);
                vbv = *(const uint4*)(v + (size_t)(tn + 2 * vkp + 1) * QLD + hh * 64 + vdc * 8);
            }

            const uint32_t* Kh = Kb + cur * 64 * AQ;
            const uint32_t* Vh = Vb + cur * 64 * AV;

            // ---- S = Q K^T ----
            float sacc[4][4];
            #pragma unroll
            for (int nt = 0; nt < 4; nt++)
                #pragma unroll
                for (int c = 0; c < 4; c++) sacc[nt][c] = 0.f;

            #pragma unroll
            for (int kk = 0; kk < 8; kk++) {
                int w0 = kk * 8 + la;
                uint32_t ah[4];
                ah[0] = Qh[rloc * AQ + w0];        ah[1] = Qh[(rloc + 8) * AQ + w0];
                ah[2] = Qh[rloc * AQ + w0 + 4];    ah[3] = Qh[(rloc + 8) * AQ + w0 + 4];
                #pragma unroll
                for (int nt = 0; nt < 4; nt++) {
                    int n0 = wn * 32 + nt * 8 + lr;
                    uint32_t bh[2] = { Kh[n0 * AQ + w0], Kh[n0 * AQ + w0 + 4] };
                    mma16816(sacc[nt], ah, bh);
                }
            }

            int rgA = qt * 64 + rloc, rgB = rgA + 8;
            #pragma unroll
            for (int nt = 0; nt < 4; nt++) {
                int cg = kt * 64 + wn * 32 + nt * 8 + 2 * la;
                sacc[nt][0] = (cg     <= rgA) ? sacc[nt][0] * scale : -1e30f;
                sacc[nt][1] = (cg + 1 <= rgA) ? sacc[nt][1] * scale : -1e30f;
                sacc[nt][2] = (cg     <= rgB) ? sacc[nt][2] * scale : -1e30f;
                sacc[nt][3] = (cg + 1 <= rgB) ? sacc[nt][3] * scale : -1e30f;
            }

            // partial max
            float mA = -1e30f, mB = -1e30f;
            #pragma unroll
            for (int nt = 0; nt < 4; nt++) {
                mA = fmaxf(mA, fmaxf(sacc[nt][0], sacc[nt][1]));
                mB = fmaxf(mB, fmaxf(sacc[nt][2], sacc[nt][3]));
            }
            mA = fmaxf(mA, __shfl_xor_sync(0xffffffff, mA, 1));
            mA = fmaxf(mA, __shfl_xor_sync(0xffffffff, mA, 2));
            mB = fmaxf(mB, __shfl_xor_sync(0xffffffff, mB, 1));
            mB = fmaxf(mB, __shfl_xor_sync(0xffffffff, mB, 2));
            if (la == 0) { pm[wn * 64 + rloc] = mA; pm[wn * 64 + rloc + 8] = mB; }
            __syncthreads();   // (1)

            float mnA = fmaxf(mstA, fmaxf(pm[rloc], pm[64 + rloc]));
            float mnB = fmaxf(mstB, fmaxf(pm[rloc + 8], pm[64 + rloc + 8]));
            float alA = __expf(mstA - mnA), alB = __expf(mstB - mnB);
            mstA = mnA; mstB = mnB;

            float sA = 0.f, sB = 0.f;
            #pragma unroll
            for (int nt = 0; nt < 4; nt++) {
                sacc[nt][0] = __expf(sacc[nt][0] - mnA);
                sacc[nt][1] = __expf(sacc[nt][1] - mnA);
                sacc[nt][2] = __expf(sacc[nt][2] - mnB);
                sacc[nt][3] = __expf(sacc[nt][3] - mnB);
                sA += sacc[nt][0] + sacc[nt][1];
                sB += sacc[nt][2] + sacc[nt][3];
            }
            sA += __shfl_xor_sync(0xffffffff, sA, 1);
            sA += __shfl_xor_sync(0xffffffff, sA, 2);
            sB += __shfl_xor_sync(0xffffffff, sB, 1);
            sB += __shfl_xor_sync(0xffffffff, sB, 2);
            if (la == 0) { ps[wn * 64 + rloc] = sA; ps[wn * 64 + rloc + 8] = sB; }

            if (pf) {  // stage V[nxt]
                const h16* pa = (const h16*)&va; const h16* pb = (const h16*)&vbv;
                uint32_t* Vn = Vb + nxt * 64 * AV;
                #pragma unroll
                for (int j = 0; j < 8; j++)
                    Vn[(vdc * 8 + j) * AV + vkp] = packh(pa[j], pb[j]);
            }
            __syncthreads();   // (2)

            lstA = lstA * alA + ps[rloc]     + ps[64 + rloc];
            lstB = lstB * alB + ps[rloc + 8] + ps[64 + rloc + 8];
            #pragma unroll
            for (int nt = 0; nt < 8; nt++) {
                oacc[nt][0] *= alA; oacc[nt][1] *= alA;
                oacc[nt][2] *= alB; oacc[nt][3] *= alB;
            }

            #pragma unroll
            for (int kc = 0; kc < 2; kc++) {
                uint32_t phi[4];
                phi[0] = pack2h(sacc[2*kc][0],   sacc[2*kc][1]);
                phi[1] = pack2h(sacc[2*kc][2],   sacc[2*kc][3]);
                phi[2] = pack2h(sacc[2*kc+1][0], sacc[2*kc+1][1]);
                phi[3] = pack2h(sacc[2*kc+1][2], sacc[2*kc+1][3]);
                int kw = wn * 16 + kc * 8 + la;
                #pragma unroll
                for (int nt = 0; nt < 8; nt++) {
                    int d0 = nt * 8 + lr;
                    uint32_t bh[2] = { Vh[d0 * AV + kw], Vh[d0 * AV + kw + 4] };
                    mma16816(oacc[nt], phi, bh);
                }
            }
            cp_wait<0>();
            __syncthreads();   // (3)
        }

        if (wn == 0 && la == 0) { rowLs[rloc] = lstA; rowLs[rloc + 8] = lstB; }
        __syncthreads();
        if (wn == 0) {
            #pragma unroll
            for (int nt = 0; nt < 8; nt++) {
                int c0 = nt * 8 + 2 * la;
                Ob[rloc * 65 + c0]         = oacc[nt][0];
                Ob[rloc * 65 + c0 + 1]     = oacc[nt][1];
                Ob[(rloc+8) * 65 + c0]     = oacc[nt][2];
                Ob[(rloc+8) * 65 + c0 + 1] = oacc[nt][3];
            }
        }
        __syncthreads();
        if (wn == 1) {
            #pragma unroll
            for (int nt = 0; nt < 8; nt++) {
                int c0 = nt * 8 + 2 * la;
                Ob[rloc * 65 + c0]         += oacc[nt][0];
                Ob[rloc * 65 + c0 + 1]     += oacc[nt][1];
                Ob[(rloc+8) * 65 + c0]     += oacc[nt][2];
                Ob[(rloc+8) * 65 + c0 + 1] += oacc[nt][3];
            }
        }
        __syncthreads();
        for (int e = tid; e < 64 * 32; e += 256) {
            int r = e >> 5, d2 = (e & 31) * 2;
            float rl = 1.f / rowLs[r];
            float v0 = Ob[r * 65 + d2]     * rl;
            float v1 = Ob[r * 65 + d2 + 1] * rl;
            size_t o = (size_t)(qt * 64 + r) * DD + hh * 64 + d2;
            *(uint32_t*)(atth + o) = pack2h(v0, v1);
        }
        __syncthreads();
    }
}

// ---- host orchestration -------------------------------------------------------------
#define SMEMSZ(BM,BN) (4 * ((BM) + (BN)) * 64)

template<int BM, int BN, bool RMS>
static void gemmT(const h16* Ah, int lda, const h16* Bh,
                  float* C, int ldc, const float* R, h16* Ch,
                  int M, int N, int K, int relu) {
    dim3 grid(N / BN, M / BM, 1);
    gemm_mma<BM, BN, RMS><<<grid, 256, SMEMSZ(BM, BN)>>>(Ah, Ah, lda, Bh, Bh, C, ldc, R, Ch, Ch, K, relu);
}
template<int BM, int BN>
static void gemmT2(const h16* Ah, const h16* Ah2, int lda,
                   const h16* Bh, const h16* Bh2,
                   h16* Ch, h16* Ch2, int ldc,
                   int M, int N, int K) {
    dim3 grid(N / BN, M / BM, 2);
    gemm_mma<BM, BN, false><<<grid, 256, SMEMSZ(BM, BN)>>>(Ah, Ah2, lda, Bh, Bh2,
                                                           nullptr, ldc, nullptr, Ch, Ch2, K, 0);
}
static void cvt1(const float* in, h16* dst, int n, int cs, int ds, int off) {
    cvt_h_s<<<dim3(2048,1,1),256>>>(in, in, dst, n, cs, ds, off, off);
}
static void cvt2(const float* in0, const float* in1, h16* dst, int n, int cs, int ds,
                 int off0, int off1) {
    cvt_h_s<<<dim3(1536,1,2),256>>>(in0, in1, dst, n, cs, ds, off0, off1);
}

extern "C" void kernel_launch(void* const* d_in, const int* in_sizes, int n_in,
                              void* d_out, int out_size) {
    const int*   idx     = (const int*)  d_in[0];
    const float* wte     = (const float*)d_in[1];
    const float* wqdown  = (const float*)d_in[2];
    const float* wqup    = (const float*)d_in[3];
    const float* wqr     = (const float*)d_in[4];
    const float* wkvdown = (const float*)d_in[5];
    const float* wkup    = (const float*)d_in[6];
    const float* wvup    = (const float*)d_in[7];
    const float* wkr     = (const float*)d_in[8];
    const float* wo      = (const float*)d_in[9];
    const float* fc1     = (const float*)d_in[10];
    const float* fc2     = (const float*)d_in[11];
    const float* lm_head = (const float*)d_in[12];
    float* out = (float*)d_out;

    cudaFuncSetAttribute((void*)gemm_mma<128,128,false>, cudaFuncAttributeMaxDynamicSharedMemorySize, SMEMSZ(128,128));
    cudaFuncSetAttribute((void*)gemm_mma<128,128,true>,  cudaFuncAttributeMaxDynamicSharedMemorySize, SMEMSZ(128,128));
    cudaFuncSetAttribute((void*)gemm_mma<128,64,true>,   cudaFuncAttributeMaxDynamicSharedMemorySize, SMEMSZ(128,64));
    cudaFuncSetAttribute((void*)gemm_mma<64,128,false>,  cudaFuncAttributeMaxDynamicSharedMemorySize, SMEMSZ(64,128));
    cudaFuncSetAttribute((void*)attn_mma,                cudaFuncAttributeMaxDynamicSharedMemorySize, ATTSM);

    void* p;
    cudaGetSymbolAddress(&p, g_x);    float* x   = (float*)p;
    cudaGetSymbolAddress(&p, g_c1h);  h16* c1h   = (h16*)p;
    cudaGetSymbolAddress(&p, g_qqr);  h16* qqr   = (h16*)p;
    cudaGetSymbolAddress(&p, g_kv);   h16* kv    = (h16*)p;
    cudaGetSymbolAddress(&p, g_atth); h16* atth  = (h16*)p;
    cudaGetSymbolAddress(&p, g_tmph); h16* tmph  = (h16*)p;
    cudaGetSymbolAddress(&p, g_xh);   h16* xh    = (h16*)p;
    cudaGetSymbolAddress(&p, g_wh);   h16* wh    = (h16*)p;

    cvt2(wqdown, wkvdown, wh+OFF_W1, NL*512*1024, 19, W1SZ, 0, 512*1024);
    cvt1(wkr,  wh+OFF_W1,  NL*64*1024,  16, W1SZ, 1024*1024);
    cvt2(wqup, wqr,  wh+OFF_W2A, NL*1024*512, 19, W2SZ, 0, 1024*512);
    cvt2(wkup, wvup, wh+OFF_W2B, NL*1024*512, 19, W2SZ, 0, 1024*512);
    cvt1(wo,      wh+OFF_WO,  NL*DD*DD, 20, DD*DD, 0);
    cvt1(fc1,     wh+OFF_FC1, NL*FF*DD, 22, FF*DD, 0);
    cvt1(fc2,     wh+OFF_FC2, NL*DD*FF, 22, DD*FF, 0);
    cvt1(lm_head, wh+OFF_LMH, VV*DD,    30, VV*DD, 0);

    embed_kernel<<<TT, 256>>>(idx, wte, x);
    rmsnorm_kernel<<<TT, 256>>>(x, x, xh);

    for (int l = 0; l < NL; l++) {
        const h16* w1  = wh + OFF_W1  + (size_t)l * W1SZ;
        const h16* w2a = wh + OFF_W2A + (size_t)l * W2SZ;
        const h16* w2b = wh + OFF_W2B + (size_t)l * W2SZ;
        const h16* wol = wh + OFF_WO  + (size_t)l * DD*DD;
        const h16* f1  = wh + OFF_FC1 + (size_t)l * FF*DD;
        const h16* f2  = wh + OFF_FC2 + (size_t)l * DD*FF;

        gemmT<128,64,true>(xh, DD, w1, nullptr, 1088, nullptr, c1h, TT, 1088, DD, 0);
        gemmT2<128,128>(c1h, c1h + 512, 1088, w2a, w2b, qqr, kv, 2048, TT, 2048, LAT);

        rope_kernel<<<dim3(TT, 17), 32>>>(qqr, c1h);

        attn_mma<<<dim3(8, 16), 256, ATTSM>>>(qqr, qqr + 1024, kv, kv + 1024, c1h + 1024, atth);

        gemmT<64,128,false>(atth, DD, wol, x, DD, x, xh, TT, DD, DD, 0);

        gemmT<128,128,true>(xh, DD, f1, nullptr, FF, nullptr, tmph, TT, FF, DD, 1);
        bool last = (l == NL - 1);
        gemmT<64,128,false>(tmph, FF, f2, x, DD, x, xh, TT, DD, FF, 0);
    }

    gemmT<128,128,false>(xh, DD, wh + OFF_LMH, out, VV, nullptr, nullptr, TT, VV, DD, 0);
}